// round 1
// baseline (speedup 1.0000x reference)
#include <cuda_runtime.h>
#include <cstddef>

// Problem constants (fixed by the dataset)
#define MROWS 8192      // B*E
#define FDIM  1024      // F
#define HDIM  512       // H
#define GDIM  2048      // 4*H
#define DSTEPS 8

// GEMM tiling
#define BM 128
#define BN 128
#define BK 16
#define TM 8
#define TN 8
#define NTHREADS 256

// Scratch (device globals: allocation-free)
__device__ float g_out[(size_t)MROWS * FDIM];     // 32 MB
__device__ float g_h[(size_t)MROWS * HDIM];       // 16 MB
__device__ float g_c[(size_t)MROWS * HDIM];       // 16 MB
__device__ float g_gates[(size_t)MROWS * GDIM];   // 64 MB

__device__ __forceinline__ float sigmoidf_(float x) {
    return 1.0f / (1.0f + __expf(-x));
}

// C[m,n] = sum_k A1[m,k]*W1[n,k] (+ sum_k A2[m,k]*W2[n,k]) + b1[n] (+ b2[n])
// A row-major [M,K], W row-major [N,K]  (i.e. C = A @ W^T, "NT" gemm).
// Optionally also writes the result to C2 with row stride ldc2.
__global__ __launch_bounds__(NTHREADS)
void gemm_nt(const float* __restrict__ A1, const float* __restrict__ W1, int K1,
             const float* __restrict__ A2, const float* __restrict__ W2, int K2,
             const float* __restrict__ b1, const float* __restrict__ b2,
             float* __restrict__ C, int ldc,
             float* __restrict__ C2, int ldc2)
{
    __shared__ float As[BK][BM + 4];
    __shared__ float Ws[BK][BN + 4];

    const int tid = threadIdx.x;
    const int bm = blockIdx.y;
    const int bn = blockIdx.x;
    const int tx = tid & 15;      // 0..15 -> column group
    const int ty = tid >> 4;      // 0..15 -> row group

    float acc[TM][TN];
#pragma unroll
    for (int i = 0; i < TM; i++)
#pragma unroll
        for (int j = 0; j < TN; j++) acc[i][j] = 0.0f;

    auto run_pass = [&](const float* __restrict__ A, const float* __restrict__ W, int K) {
        for (int k0 = 0; k0 < K; k0 += BK) {
            // Stage BM x BK of A and BN x BK of W into smem (transposed), float4 loads.
#pragma unroll
            for (int it = 0; it < 2; it++) {
                int idx = tid + it * NTHREADS;     // 0..511
                int row = idx >> 2;                // 0..127
                int c4  = (idx & 3) * 4;           // 0,4,8,12
                const float4 va = *(const float4*)(A + (size_t)(bm * BM + row) * K + k0 + c4);
                As[c4 + 0][row] = va.x;
                As[c4 + 1][row] = va.y;
                As[c4 + 2][row] = va.z;
                As[c4 + 3][row] = va.w;
                const float4 vw = *(const float4*)(W + (size_t)(bn * BN + row) * K + k0 + c4);
                Ws[c4 + 0][row] = vw.x;
                Ws[c4 + 1][row] = vw.y;
                Ws[c4 + 2][row] = vw.z;
                Ws[c4 + 3][row] = vw.w;
            }
            __syncthreads();

#pragma unroll
            for (int k = 0; k < BK; k++) {
                float4 a0 = *(const float4*)&As[k][ty * TM];
                float4 a1 = *(const float4*)&As[k][ty * TM + 4];
                float4 w0 = *(const float4*)&Ws[k][tx * TN];
                float4 w1 = *(const float4*)&Ws[k][tx * TN + 4];
                float a[TM] = {a0.x, a0.y, a0.z, a0.w, a1.x, a1.y, a1.z, a1.w};
                float w[TN] = {w0.x, w0.y, w0.z, w0.w, w1.x, w1.y, w1.z, w1.w};
#pragma unroll
                for (int i = 0; i < TM; i++)
#pragma unroll
                    for (int j = 0; j < TN; j++)
                        acc[i][j] = fmaf(a[i], w[j], acc[i][j]);
            }
            __syncthreads();
        }
    };

    run_pass(A1, W1, K1);
    if (A2) run_pass(A2, W2, K2);

    // Epilogue: add bias, write C (and optionally C2) with float4 stores.
    float bcol[TN];
#pragma unroll
    for (int j = 0; j < TN; j++) {
        int col = bn * BN + tx * TN + j;
        float bv = b1 ? b1[col] : 0.0f;
        if (b2) bv += b2[col];
        bcol[j] = bv;
    }

#pragma unroll
    for (int i = 0; i < TM; i++) {
        int row = bm * BM + ty * TM + i;
        int col0 = bn * BN + tx * TN;
#pragma unroll
        for (int j4 = 0; j4 < TN; j4 += 4) {
            float4 v;
            v.x = acc[i][j4 + 0] + bcol[j4 + 0];
            v.y = acc[i][j4 + 1] + bcol[j4 + 1];
            v.z = acc[i][j4 + 2] + bcol[j4 + 2];
            v.w = acc[i][j4 + 3] + bcol[j4 + 3];
            *(float4*)(C + (size_t)row * ldc + col0 + j4) = v;
            if (C2)
                *(float4*)(C2 + (size_t)row * ldc2 + col0 + j4) = v;
        }
    }
}

// Elementwise LSTM cell: gates [M, 4H] (order i,f,g,o), updates h,c [M,H].
__global__ void lstm_cell(const float* __restrict__ gates,
                          float* __restrict__ h, float* __restrict__ c,
                          int first)
{
    int idx = blockIdx.x * blockDim.x + threadIdx.x;   // 0 .. M*H-1
    int row = idx >> 9;          // / HDIM (512)
    int j   = idx & (HDIM - 1);
    const float* g = gates + (size_t)row * GDIM;
    float ig = sigmoidf_(g[j]);
    float fg = sigmoidf_(g[HDIM + j]);
    float gg = tanhf(g[2 * HDIM + j]);
    float og = sigmoidf_(g[3 * HDIM + j]);
    float cold = first ? 0.0f : c[idx];
    float cn = fg * cold + ig * gg;
    c[idx] = cn;
    h[idx] = og * tanhf(cn);
}

extern "C" void kernel_launch(void* const* d_in, const int* in_sizes, int n_in,
                              void* d_out, int out_size)
{
    const float* x     = (const float*)d_in[0];   // [B,E,F] = [8192,1024]
    const float* W_ih  = (const float*)d_in[1];   // [2048,1024]
    const float* W_hh  = (const float*)d_in[2];   // [2048,512]
    const float* b_ih  = (const float*)d_in[3];   // [2048]
    const float* b_hh  = (const float*)d_in[4];   // [2048]
    const float* W_cls = (const float*)d_in[5];   // [1024,512]
    const float* b_cls = (const float*)d_in[6];   // [1024]
    float* out = (float*)d_out;                   // [B,E,D,F] -> [8192, 8, 1024]

    float *p_out, *p_h, *p_c, *p_gates;
    cudaGetSymbolAddress((void**)&p_out,   g_out);
    cudaGetSymbolAddress((void**)&p_h,     g_h);
    cudaGetSymbolAddress((void**)&p_c,     g_c);
    cudaGetSymbolAddress((void**)&p_gates, g_gates);

    dim3 gridG(GDIM / BN, MROWS / BM);   // (16, 64)
    dim3 gridC(FDIM / BN, MROWS / BM);   // (8, 64)
    int cellBlocks = (MROWS * HDIM) / NTHREADS;

    for (int d = 0; d < DSTEPS; d++) {
        const float* Ain = (d == 0) ? x : p_out;
        const float* A2  = (d == 0) ? nullptr : p_h;
        // gates = Ain @ W_ih^T + h @ W_hh^T + (b_ih + b_hh)
        gemm_nt<<<gridG, NTHREADS>>>(Ain, W_ih, FDIM,
                                     A2, W_hh, HDIM,
                                     b_ih, b_hh,
                                     p_gates, GDIM,
                                     nullptr, 0);
        // cell update
        lstm_cell<<<cellBlocks, NTHREADS>>>(p_gates, p_h, p_c, d == 0 ? 1 : 0);
        // out = h @ W_cls^T + b_cls  (also scatter to d_out slice d)
        gemm_nt<<<gridC, NTHREADS>>>(p_h, W_cls, HDIM,
                                     nullptr, nullptr, 0,
                                     b_cls, nullptr,
                                     p_out, FDIM,
                                     out + (size_t)d * FDIM, DSTEPS * FDIM);
    }
}

// round 3
// speedup vs baseline: 2.1022x; 2.1022x over previous
#include <cuda_runtime.h>
#include <cuda_bf16.h>
#include <cstdint>
#include <cstddef>

// ---------------- problem constants ----------------
#define MROWS 8192
#define FDIM  1024
#define HDIM  512
#define GDIM  2048
#define KFUSE 1536     // F + H fused K for the gates GEMM
#define DSTEPS 8

// ---------------- GEMM tile config ----------------
#define BM 128
#define BN 128
#define BK 32                 // bf16 elems per chunk (64 bytes per row)
#define STAGES 3
#define TILE_B 8192           // 128 rows * 64 B
#define STAGE_B (4*TILE_B)    // Ahi, Alo, Whi, Wlo
#define SMEM_TOTAL (STAGES*STAGE_B)   // 98304

// ---------------- scratch (device globals) ----------------
__device__ __align__(256) __nv_bfloat16 g_act_hi[(size_t)MROWS*KFUSE];
__device__ __align__(256) __nv_bfloat16 g_act_lo[(size_t)MROWS*KFUSE];
__device__ __align__(256) __nv_bfloat16 g_wg_hi[(size_t)GDIM*KFUSE];
__device__ __align__(256) __nv_bfloat16 g_wg_lo[(size_t)GDIM*KFUSE];
__device__ __align__(256) __nv_bfloat16 g_wc_hi[(size_t)FDIM*HDIM];
__device__ __align__(256) __nv_bfloat16 g_wc_lo[(size_t)FDIM*HDIM];
__device__ __align__(256) float g_gates[(size_t)MROWS*GDIM];
__device__ __align__(256) float g_c[(size_t)MROWS*HDIM];

// ---------------- helpers ----------------
__device__ __forceinline__ uint32_t smem_u32(const void* p) {
    uint32_t a;
    asm("{ .reg .u64 t; cvta.to.shared.u64 t, %1; cvt.u32.u64 %0, t; }" : "=r"(a) : "l"(p));
    return a;
}
__device__ __forceinline__ void cp16(uint32_t dst, const void* src) {
    asm volatile("cp.async.cg.shared.global [%0], [%1], 16;" :: "r"(dst), "l"(src) : "memory");
}
#define CP_COMMIT() asm volatile("cp.async.commit_group;" ::: "memory")
#define CP_WAIT1()  asm volatile("cp.async.wait_group 1;" ::: "memory")

__device__ __forceinline__ void ldsm4(uint32_t addr, uint32_t& r0, uint32_t& r1, uint32_t& r2, uint32_t& r3) {
    asm volatile("ldmatrix.sync.aligned.m8n8.x4.shared.b16 {%0,%1,%2,%3}, [%4];"
                 : "=r"(r0), "=r"(r1), "=r"(r2), "=r"(r3) : "r"(addr));
}
__device__ __forceinline__ void mma16816(float* c, const uint32_t* a, const uint32_t* b) {
    asm volatile("mma.sync.aligned.m16n8k16.row.col.f32.bf16.bf16.f32 "
                 "{%0,%1,%2,%3}, {%4,%5,%6,%7}, {%8,%9}, {%0,%1,%2,%3};"
                 : "+f"(c[0]), "+f"(c[1]), "+f"(c[2]), "+f"(c[3])
                 : "r"(a[0]), "r"(a[1]), "r"(a[2]), "r"(a[3]), "r"(b[0]), "r"(b[1]));
}
__device__ __forceinline__ void split2(float v, __nv_bfloat16& hi, __nv_bfloat16& lo) {
    hi = __float2bfloat16(v);
    lo = __float2bfloat16(v - __bfloat162float(hi));
}
__device__ __forceinline__ float sigmoidf_(float x) { return 1.0f / (1.0f + __expf(-x)); }

// swizzled byte offset within a 128-row x 64-byte tile: row r, 16B chunk c (0..3)
__device__ __forceinline__ uint32_t swz(int r, int c) {
    return (uint32_t)(r * 64 + ((c ^ ((r >> 1) & 3)) << 4));
}

// ---------------- split-precision HMMA GEMM ----------------
// C[M,N] = (Ahi+Alo)[M,K] @ (Whi+Wlo)[N,K]^T + bias  (3 bf16 mma passes)
// mode 0: write Cg (ld=GDIM), bias = b1+b2
// mode 1: write Co (ld=DSTEPS*FDIM), bias = b1; also split-write into act_hi/lo
__global__ void __launch_bounds__(256, 1)
gemm_hmma(const __nv_bfloat16* __restrict__ Ahi, const __nv_bfloat16* __restrict__ Alo, int lda,
          const __nv_bfloat16* __restrict__ Whi, const __nv_bfloat16* __restrict__ Wlo, int ldw,
          int K,
          const float* __restrict__ b1, const float* __restrict__ b2,
          float* __restrict__ Cg, float* __restrict__ Co,
          __nv_bfloat16* __restrict__ act_hi, __nv_bfloat16* __restrict__ act_lo,
          int mode)
{
    extern __shared__ char smem[];
    const uint32_t sb = smem_u32(smem);
    const int tid = threadIdx.x;
    const int lane = tid & 31;
    const int wid = tid >> 5;
    const int wm = wid & 1;        // 0..1 -> 64-row half
    const int wn = wid >> 1;       // 0..3 -> 32-col quarter
    const int bm = blockIdx.y, bn = blockIdx.x;
    const int nch = K / BK;

    const char* srcT[4];
    srcT[0] = (const char*)Ahi + (size_t)(bm * BM) * lda * 2;
    srcT[1] = (const char*)Alo + (size_t)(bm * BM) * lda * 2;
    srcT[2] = (const char*)Whi + (size_t)(bn * BN) * ldw * 2;
    srcT[3] = (const char*)Wlo + (size_t)(bn * BN) * ldw * 2;
    const size_t ldab = (size_t)lda * 2, ldwb = (size_t)ldw * 2;

    // loader: 2048 granules of 16B per stage, 8 per thread; tile = compile-time
    auto load_stage = [&](int slot, int chunk) {
        const uint32_t stg = sb + slot * STAGE_B;
        const int kb = chunk * (BK * 2);   // byte offset along K
#pragma unroll
        for (int t = 0; t < 4; t++) {
            const size_t ldb = (t < 2) ? ldab : ldwb;
#pragma unroll
            for (int half = 0; half < 2; half++) {
                const int idx = tid + half * 256;   // 0..511
                const int r = idx >> 2, c = idx & 3;
                cp16(stg + t * TILE_B + swz(r, c),
                     srcT[t] + (size_t)r * ldb + kb + c * 16);
            }
        }
    };

    float acc[4][4][4];
#pragma unroll
    for (int mt = 0; mt < 4; mt++)
#pragma unroll
        for (int nt = 0; nt < 4; nt++)
#pragma unroll
            for (int e = 0; e < 4; e++) acc[mt][nt][e] = 0.0f;

    // prefetch 2 chunks
    load_stage(0, 0); CP_COMMIT();
    load_stage(1, 1); CP_COMMIT();

    // ldmatrix per-thread row/chunk pattern (identical for A and B tiles):
    // lanes 0-15 -> rows rbase+0..15 chunk cc; lanes 16-31 -> same rows chunk cc+1
    const int lrow = lane & 15;
    const int lchk = lane >> 4;

    for (int i = 0; i < nch; i++) {
        CP_WAIT1();
        __syncthreads();
        if (i + 2 < nch) load_stage((i + 2) % STAGES, i + 2);
        CP_COMMIT();

        const uint32_t stg = sb + (i % STAGES) * STAGE_B;
        const uint32_t sA_hi = stg;
        const uint32_t sA_lo = stg + TILE_B;
        const uint32_t sW_hi = stg + 2 * TILE_B;
        const uint32_t sW_lo = stg + 3 * TILE_B;

#pragma unroll
        for (int kh = 0; kh < 2; kh++) {
            const int cc = kh * 2 + lchk;
            uint32_t ah[4][4], al[4][4], bh[4][2], bl[4][2];
#pragma unroll
            for (int mt = 0; mt < 4; mt++) {
                const int r = wm * 64 + mt * 16 + lrow;
                const uint32_t off = swz(r, cc);
                ldsm4(sA_hi + off, ah[mt][0], ah[mt][1], ah[mt][2], ah[mt][3]);
                ldsm4(sA_lo + off, al[mt][0], al[mt][1], al[mt][2], al[mt][3]);
            }
#pragma unroll
            for (int np = 0; np < 2; np++) {
                const int r = wn * 32 + np * 16 + lrow;
                const uint32_t off = swz(r, cc);
                uint32_t r0, r1, r2, r3;
                ldsm4(sW_hi + off, r0, r1, r2, r3);
                bh[np * 2][0] = r0; bh[np * 2 + 1][0] = r1;
                bh[np * 2][1] = r2; bh[np * 2 + 1][1] = r3;
                ldsm4(sW_lo + off, r0, r1, r2, r3);
                bl[np * 2][0] = r0; bl[np * 2 + 1][0] = r1;
                bl[np * 2][1] = r2; bl[np * 2 + 1][1] = r3;
            }
#pragma unroll
            for (int mt = 0; mt < 4; mt++)
#pragma unroll
                for (int nt = 0; nt < 4; nt++) {
                    mma16816(acc[mt][nt], ah[mt], bh[nt]);   // hi*hi
                    mma16816(acc[mt][nt], al[mt], bh[nt]);   // lo*hi
                    mma16816(acc[mt][nt], ah[mt], bl[nt]);   // hi*lo
                }
        }
        __syncthreads();
    }

    // ---------------- epilogue ----------------
    const int rbase = bm * BM + wm * 64;
    const int cbase = bn * BN + wn * 32;
    const int qr = lane >> 2;            // 0..7
    const int qc = (lane & 3) * 2;       // 0,2,4,6

#pragma unroll
    for (int mt = 0; mt < 4; mt++) {
#pragma unroll
        for (int nt = 0; nt < 4; nt++) {
            const int col = cbase + nt * 8 + qc;
            float bv0, bv1;
            if (mode == 0) {
                bv0 = b1[col] + b2[col];
                bv1 = b1[col + 1] + b2[col + 1];
            } else {
                bv0 = b1[col];
                bv1 = b1[col + 1];
            }
#pragma unroll
            for (int half = 0; half < 2; half++) {
                const int row = rbase + mt * 16 + qr + half * 8;
                float v0 = acc[mt][nt][half * 2 + 0] + bv0;
                float v1 = acc[mt][nt][half * 2 + 1] + bv1;
                if (mode == 0) {
                    *(float2*)(Cg + (size_t)row * GDIM + col) = make_float2(v0, v1);
                } else {
                    *(float2*)(Co + (size_t)row * (DSTEPS * FDIM) + col) = make_float2(v0, v1);
                    __nv_bfloat16 h0, l0, h1, l1;
                    split2(v0, h0, l0);
                    split2(v1, h1, l1);
                    *(__nv_bfloat162*)(act_hi + (size_t)row * KFUSE + col) = __nv_bfloat162(h0, h1);
                    *(__nv_bfloat162*)(act_lo + (size_t)row * KFUSE + col) = __nv_bfloat162(l0, l1);
                }
            }
        }
    }
}

// ---------------- elementwise kernels ----------------
__global__ void split_act(const float* __restrict__ x,
                          __nv_bfloat16* __restrict__ ah, __nv_bfloat16* __restrict__ al)
{
    const int idx = blockIdx.x * blockDim.x + threadIdx.x;   // MROWS*KFUSE
    const int row = idx / KFUSE, col = idx - row * KFUSE;
    float v = (col < FDIM) ? x[(size_t)row * FDIM + col] : 0.0f;
    __nv_bfloat16 hi, lo; split2(v, hi, lo);
    ah[idx] = hi; al[idx] = lo;
}

__global__ void split_weights(const float* __restrict__ W_ih, const float* __restrict__ W_hh,
                              const float* __restrict__ W_cls,
                              __nv_bfloat16* __restrict__ wgh, __nv_bfloat16* __restrict__ wgl,
                              __nv_bfloat16* __restrict__ wch, __nv_bfloat16* __restrict__ wcl)
{
    const int idx = blockIdx.x * blockDim.x + threadIdx.x;
    const int NG = GDIM * KFUSE;
    if (idx < NG) {
        const int n = idx / KFUSE, col = idx - n * KFUSE;
        float v = (col < FDIM) ? W_ih[(size_t)n * FDIM + col]
                               : W_hh[(size_t)n * HDIM + (col - FDIM)];
        __nv_bfloat16 hi, lo; split2(v, hi, lo);
        wgh[idx] = hi; wgl[idx] = lo;
    } else {
        const int i2 = idx - NG;                // FDIM*HDIM
        float v = W_cls[i2];
        __nv_bfloat16 hi, lo; split2(v, hi, lo);
        wch[i2] = hi; wcl[i2] = lo;
    }
}

__global__ void lstm_cell(const float* __restrict__ gates,
                          __nv_bfloat16* __restrict__ ah, __nv_bfloat16* __restrict__ al,
                          float* __restrict__ c, int first)
{
    const int idx = blockIdx.x * blockDim.x + threadIdx.x;   // MROWS*HDIM
    const int row = idx >> 9, j = idx & (HDIM - 1);
    const float* g = gates + (size_t)row * GDIM;
    const float ig = sigmoidf_(g[j]);
    const float fg = sigmoidf_(g[HDIM + j]);
    const float gg = tanhf(g[2 * HDIM + j]);
    const float og = sigmoidf_(g[3 * HDIM + j]);
    const float cold = first ? 0.0f : c[idx];
    const float cn = fg * cold + ig * gg;
    c[idx] = cn;
    const float h = og * tanhf(cn);
    __nv_bfloat16 hi, lo; split2(h, hi, lo);
    ah[(size_t)row * KFUSE + FDIM + j] = hi;
    al[(size_t)row * KFUSE + FDIM + j] = lo;
}

// ---------------- launch ----------------
extern "C" void kernel_launch(void* const* d_in, const int* in_sizes, int n_in,
                              void* d_out, int out_size)
{
    const float* x     = (const float*)d_in[0];
    const float* W_ih  = (const float*)d_in[1];
    const float* W_hh  = (const float*)d_in[2];
    const float* b_ih  = (const float*)d_in[3];
    const float* b_hh  = (const float*)d_in[4];
    const float* W_cls = (const float*)d_in[5];
    const float* b_cls = (const float*)d_in[6];
    float* out = (float*)d_out;                    // [8192 rows, 8 steps, 1024]

    __nv_bfloat16 *p_ah, *p_al, *p_wgh, *p_wgl, *p_wch, *p_wcl;
    float *p_gates, *p_c;
    cudaGetSymbolAddress((void**)&p_ah,  g_act_hi);
    cudaGetSymbolAddress((void**)&p_al,  g_act_lo);
    cudaGetSymbolAddress((void**)&p_wgh, g_wg_hi);
    cudaGetSymbolAddress((void**)&p_wgl, g_wg_lo);
    cudaGetSymbolAddress((void**)&p_wch, g_wc_hi);
    cudaGetSymbolAddress((void**)&p_wcl, g_wc_lo);
    cudaGetSymbolAddress((void**)&p_gates, g_gates);
    cudaGetSymbolAddress((void**)&p_c,   g_c);

    cudaFuncSetAttribute(gemm_hmma, cudaFuncAttributeMaxDynamicSharedMemorySize, SMEM_TOTAL);

    split_act<<<(MROWS * KFUSE) / 256, 256>>>(x, p_ah, p_al);
    split_weights<<<(GDIM * KFUSE + FDIM * HDIM) / 256, 256>>>(W_ih, W_hh, W_cls,
                                                               p_wgh, p_wgl, p_wch, p_wcl);

    const dim3 gridG(GDIM / BN, MROWS / BM);   // (16, 64)
    const dim3 gridC(FDIM / BN, MROWS / BM);   // (8, 64)
    const int cellBlocks = (MROWS * HDIM) / 256;

    for (int d = 0; d < DSTEPS; d++) {
        // gates = act @ Wg^T + (b_ih + b_hh)   (fused K = 1536)
        gemm_hmma<<<gridG, 256, SMEM_TOTAL>>>(p_ah, p_al, KFUSE,
                                              p_wgh, p_wgl, KFUSE,
                                              KFUSE, b_ih, b_hh,
                                              p_gates, nullptr, nullptr, nullptr, 0);
        lstm_cell<<<cellBlocks, 256>>>(p_gates, p_ah, p_al, p_c, d == 0 ? 1 : 0);
        // out = h @ W_cls^T + b_cls -> d_out slice d; re-split into act cols [0,1024)
        gemm_hmma<<<gridC, 256, SMEM_TOTAL>>>(p_ah + FDIM, p_al + FDIM, KFUSE,
                                              p_wch, p_wcl, HDIM,
                                              HDIM, b_cls, nullptr,
                                              nullptr, out + (size_t)d * FDIM,
                                              p_ah, p_al, 1);
    }
}